// round 12
// baseline (speedup 1.0000x reference)
#include <cuda_runtime.h>
#include <cuda_bf16.h>
#include <cstdint>

#define N_TOK 131072
#define DIM   64
#define QSTG  8
#define KCB   1024

#define TM       128            // tokens per CTA (MMA M)
#define NB       128            // codewords per block (MMA N per block)
#define BPS      (KCB / NB)     // 8 blocks per stage
#define NGBLK    (QSTG * BPS)   // 64
#define NTHREADS 256
#define SA_ROWF  66

#define MARG_CONST 2.5e-4f

typedef unsigned int uint;

// ---- smem layout (bytes) ----
// B images: 2 x (128 rows x 272B)   row: [hi 128B | lo 128B | pad 16B]
// A image : 128 rows x 272B, same format
// 272B stride = 68 banks == 4 (mod 32) -> fragment loads conflict-free
#define BIMG0_B  0
#define BIMG_SZ  (128 * 272)            // 34816
#define BIMG1_B  BIMG_SZ
#define AIMG_B   (2 * BIMG_SZ)          // 69632
#define SA_B     (AIMG_B + BIMG_SZ)     // 104448
#define SCN_B    (SA_B + TM * SA_ROWF * 4)   // 138240
#define REDM1_B  (SCN_B + 4096)         // 142336
#define REDM2_B  (REDM1_B + 4096)
#define REDI_B   (REDM2_B + 4096)
#define RSCV_B   (REDI_B + 4096)        // 154624
#define RSCI_B   (RSCV_B + 1024)
#define SMEM_BYTES (RSCI_B + 1024)      // 156672

__device__ double g_loss[QSTG];
__device__ float  g_cnorm[QSTG * KCB];
__device__ int    g_maxcn[QSTG];
__device__ float  g_cbB[(size_t)NGBLK * 8192];   // 64 blocks x 32KB images

__device__ __forceinline__ void cp_async16(uint dst, const void* src) {
    asm volatile("cp.async.cg.shared.global [%0], [%1], 16;" :: "r"(dst), "l"(src));
}
__device__ __forceinline__ void cp_commit() { asm volatile("cp.async.commit_group;"); }
template <int N> __device__ __forceinline__ void cp_wait() {
    asm volatile("cp.async.wait_group %0;" :: "n"(N));
}
__device__ __forceinline__ void mma16816(float* d, uint a0, uint a1, uint a2, uint a3,
                                         uint b0, uint b1) {
    asm volatile("mma.sync.aligned.m16n8k16.row.col.f32.bf16.bf16.f32 "
                 "{%0,%1,%2,%3}, {%4,%5,%6,%7}, {%8,%9}, {%0,%1,%2,%3};"
                 : "+f"(d[0]), "+f"(d[1]), "+f"(d[2]), "+f"(d[3])
                 : "r"(a0), "r"(a1), "r"(a2), "r"(a3), "r"(b0), "r"(b1));
}
__device__ __forceinline__ uint pack_bf16x2(float x0, float x1) {
    __nv_bfloat16 h0 = __float2bfloat16_rn(x0);
    __nv_bfloat16 h1 = __float2bfloat16_rn(x1);
    return (uint)__bfloat16_as_ushort(h0) | ((uint)__bfloat16_as_ushort(h1) << 16);
}

// ---------------------------------------------------------------------------
// prep1: codeword norms (verified pipeline) + per-stage max norm + zero losses
// ---------------------------------------------------------------------------
__global__ void prep_kernel(const float* __restrict__ cb) {
    int k = blockIdx.x * blockDim.x + threadIdx.x;
    if (k < QSTG * KCB) {
        const float* p = cb + (size_t)k * DIM;
        float s0 = 0.f, s1 = 0.f, s2 = 0.f, s3 = 0.f;
#pragma unroll
        for (int d = 0; d < DIM; d += 4) {
            s0 = __fadd_rn(s0, __fmul_rn(p[d + 0], p[d + 0]));
            s1 = __fadd_rn(s1, __fmul_rn(p[d + 1], p[d + 1]));
            s2 = __fadd_rn(s2, __fmul_rn(p[d + 2], p[d + 2]));
            s3 = __fadd_rn(s3, __fmul_rn(p[d + 3], p[d + 3]));
        }
        float cn = __fadd_rn(__fadd_rn(s0, s1), __fadd_rn(s2, s3));
        g_cnorm[k] = cn;
        atomicMax(&g_maxcn[k / KCB], __float_as_int(cn));   // positive floats
    }
    if (blockIdx.x == 0 && threadIdx.x < QSTG) g_loss[threadIdx.x] = 0.0;
}

// ---------------------------------------------------------------------------
// prep2: bf16 hi/lo images of codebook blocks (128 rows x 256B: hi128|lo128)
// ---------------------------------------------------------------------------
__global__ void prep_bimg_kernel(const float* __restrict__ cb) {
    const int g   = blockIdx.x;
    const int tid = threadIdx.x;
    char* img = (char*)(g_cbB + (size_t)g * 8192);
    const float* src = cb + (size_t)g * NB * DIM;
#pragma unroll
    for (int it = 0; it < 16; ++it) {
        int u = it * NTHREADS + tid;          // 0..4095 : (row, d-pair)
        int kr = u >> 5, dp = (u & 31) * 2;
        float c0 = src[kr * DIM + dp], c1 = src[kr * DIM + dp + 1];
        __nv_bfloat16 h0 = __float2bfloat16_rn(c0);
        __nv_bfloat16 h1 = __float2bfloat16_rn(c1);
        uint hw = (uint)__bfloat16_as_ushort(h0) | ((uint)__bfloat16_as_ushort(h1) << 16);
        uint lw = pack_bf16x2(c0 - __bfloat162float(h0), c1 - __bfloat162float(h1));
        *(uint*)(img + kr * 256 + dp * 2)       = hw;
        *(uint*)(img + kr * 256 + 128 + dp * 2) = lw;
    }
}

// ---------------------------------------------------------------------------
// register-free staging: 32KB image -> padded 272B-row smem tile
// ---------------------------------------------------------------------------
__device__ __forceinline__ void prefetch_blk(uint buf_base, int g, int tid) {
    const char* src = (const char*)(g_cbB + (size_t)g * 8192);
#pragma unroll
    for (int s = 0; s < 8; ++s) {
        int i = tid + NTHREADS * s;           // 16B units 0..2047
        cp_async16(buf_base + (uint)(i >> 4) * 272 + (uint)(i & 15) * 16,
                   src + (size_t)i * 16);
    }
    cp_commit();
}

// argmin fold state update (k ascending => first-min wins via strict <)
#define UPD(m1, m2, i1, v, k) do {                         \
    if ((v) < (m1)) { (m2) = (m1); (m1) = (v); (i1) = (k); } \
    else if ((v) < (m2)) (m2) = (v);                        \
} while (0)

// ---------------------------------------------------------------------------
// main fused kernel: hi/lo bf16 mma.sync distances + margin + exact rescue
// ---------------------------------------------------------------------------
__global__ void __launch_bounds__(NTHREADS, 1)
vq_kernel(const float* __restrict__ x, const float* __restrict__ cb,
          float* __restrict__ out) {
    extern __shared__ char smc[];
    char*  aimg = smc + AIMG_B;
    float* sA   = (float*)(smc + SA_B);
    float* sCn  = (float*)(smc + SCN_B);
    float* redM1 = (float*)(smc + REDM1_B);
    float* redM2 = (float*)(smc + REDM2_B);
    int*   redI  = (int*)(smc + REDI_B);
    float* rscV  = (float*)(smc + RSCV_B);
    int*   rscI  = (int*)(smc + RSCI_B);
    __shared__ int   finIdx[TM];
    __shared__ int   list[TM];
    __shared__ int   cnt;
    __shared__ float wsum[NTHREADS / 32];

    const int tid  = threadIdx.x;
    const int lane = tid & 31, wid = tid >> 5;
    const int wm = wid & 3, wn = wid >> 2;       // 4 x 2 warp grid
    const int g8 = lane >> 2, c4 = lane & 3;
    const int n0 = blockIdx.x * TM;
    const uint smem_base = (uint)__cvta_generic_to_shared((void*)smc);

    float* out_xq  = out;
    float* out_idx = out + (size_t)N_TOK * DIM;

    // ---- load fp32 residual tile ----
    {
        const int t = tid >> 1, hd = tid & 1;
        const float2* xr = (const float2*)(x + (size_t)(n0 + t) * DIM + hd * 32);
        float2* ar = (float2*)(sA + t * SA_ROWF + hd * 32);
#pragma unroll
        for (int m = 0; m < 16; ++m) ar[m] = xr[m];
    }

    // ---- prefetch B blocks 0,1 ----
    prefetch_blk(smem_base + BIMG0_B, 0, tid);
    prefetch_blk(smem_base + BIMG1_B, 1, tid);

    for (int q = 0; q < QSTG; ++q) {
        const float* cbq = cb + (size_t)q * KCB * DIM;

        // ---- residual -> bf16 hi/lo A image (row t: hi bytes 0-127, lo 128-255) ----
        {
            const int t = tid >> 1, hd = tid & 1;
            const float* rr = sA + t * SA_ROWF + hd * 32;
            char* arow = aimg + t * 272;
#pragma unroll
            for (int dp = 0; dp < 16; ++dp) {
                float r0 = rr[2 * dp], r1 = rr[2 * dp + 1];
                __nv_bfloat16 h0 = __float2bfloat16_rn(r0);
                __nv_bfloat16 h1 = __float2bfloat16_rn(r1);
                uint hw = (uint)__bfloat16_as_ushort(h0) | ((uint)__bfloat16_as_ushort(h1) << 16);
                uint lw = pack_bf16x2(r0 - __bfloat162float(h0), r1 - __bfloat162float(h1));
                int d0 = hd * 32 + dp * 2;
                *(uint*)(arow + d0 * 2)       = hw;
                *(uint*)(arow + 128 + d0 * 2) = lw;
            }
        }
#pragma unroll
        for (int s = 0; s < 4; ++s)
            sCn[tid + s * NTHREADS] = g_cnorm[q * KCB + tid + s * NTHREADS];
        __syncthreads();   // A image + cnorms ready

        // ---- load A fragments for the stage (hi & lo, cached in regs) ----
        uint Ah[2][4][4], Al[2][4][4];
#pragma unroll
        for (int mt = 0; mt < 2; ++mt) {
            const char* base0 = aimg + (wm * 32 + mt * 16 + g8) * 272 + c4 * 4;
#pragma unroll
            for (int ks = 0; ks < 4; ++ks) {
                const char* bh = base0 + ks * 32;
                Ah[mt][ks][0] = *(const uint*)(bh);
                Ah[mt][ks][2] = *(const uint*)(bh + 16);
                Ah[mt][ks][1] = *(const uint*)(bh + 8 * 272);
                Ah[mt][ks][3] = *(const uint*)(bh + 8 * 272 + 16);
                const char* bl = bh + 128;
                Al[mt][ks][0] = *(const uint*)(bl);
                Al[mt][ks][2] = *(const uint*)(bl + 16);
                Al[mt][ks][1] = *(const uint*)(bl + 8 * 272);
                Al[mt][ks][3] = *(const uint*)(bl + 8 * 272 + 16);
            }
        }

        float fm1[4], fm2[4];
        int   fi1[4];
#pragma unroll
        for (int i = 0; i < 4; ++i) { fm1[i] = 3.4e38f; fm2[i] = 3.4e38f; fi1[i] = 0; }

        for (int b = 0; b < BPS; ++b) {
            const int g = q * BPS + b;
            if (g == NGBLK - 1) cp_wait<0>(); else cp_wait<1>();
            __syncthreads();   // block g resident

            const char* bimg = smc + ((g & 1) ? BIMG1_B : BIMG0_B);

            float acc[2][8][4];
#pragma unroll
            for (int mt = 0; mt < 2; ++mt)
#pragma unroll
                for (int nt = 0; nt < 8; ++nt)
#pragma unroll
                    for (int r = 0; r < 4; ++r) acc[mt][nt][r] = 0.f;

            // ---- 3 split-products: hh, hl, lh ----
#pragma unroll
            for (int s = 0; s < 3; ++s) {
                const int bOff = (s == 1) ? 128 : 0;    // B lo for hl
#pragma unroll
                for (int ks = 0; ks < 4; ++ks) {
#pragma unroll
                    for (int nt = 0; nt < 8; ++nt) {
                        const char* bb = bimg + (wn * 64 + nt * 8 + g8) * 272
                                         + bOff + ks * 32 + c4 * 4;
                        uint b0 = *(const uint*)(bb);
                        uint b1 = *(const uint*)(bb + 16);
                        if (s == 2) {
                            mma16816(acc[0][nt], Al[0][ks][0], Al[0][ks][1],
                                     Al[0][ks][2], Al[0][ks][3], b0, b1);
                            mma16816(acc[1][nt], Al[1][ks][0], Al[1][ks][1],
                                     Al[1][ks][2], Al[1][ks][3], b0, b1);
                        } else {
                            mma16816(acc[0][nt], Ah[0][ks][0], Ah[0][ks][1],
                                     Ah[0][ks][2], Ah[0][ks][3], b0, b1);
                            mma16816(acc[1][nt], Ah[1][ks][0], Ah[1][ks][1],
                                     Ah[1][ks][2], Ah[1][ks][3], b0, b1);
                        }
                    }
                }
            }

            // ---- fold distances (k ascending) ----
            const int kbase = b * NB + wn * 64;
#pragma unroll
            for (int mt = 0; mt < 2; ++mt)
#pragma unroll
                for (int nt = 0; nt < 8; ++nt) {
                    int kb = kbase + nt * 8 + c4 * 2;
                    float2 cn = *(float2*)(sCn + kb);
                    float v0 = fmaf(-2.f, acc[mt][nt][0], cn.x);
                    float v1 = fmaf(-2.f, acc[mt][nt][1], cn.y);
                    UPD(fm1[mt * 2 + 0], fm2[mt * 2 + 0], fi1[mt * 2 + 0], v0, kb);
                    UPD(fm1[mt * 2 + 0], fm2[mt * 2 + 0], fi1[mt * 2 + 0], v1, kb + 1);
                    float v2 = fmaf(-2.f, acc[mt][nt][2], cn.x);
                    float v3 = fmaf(-2.f, acc[mt][nt][3], cn.y);
                    UPD(fm1[mt * 2 + 1], fm2[mt * 2 + 1], fi1[mt * 2 + 1], v2, kb);
                    UPD(fm1[mt * 2 + 1], fm2[mt * 2 + 1], fi1[mt * 2 + 1], v3, kb + 1);
                }

            __syncthreads();   // done reading buffer (g&1)
            if (g + 2 < NGBLK)
                prefetch_blk(smem_base + ((g & 1) ? BIMG1_B : BIMG0_B), g + 2, tid);
        }

        // ---- write 8 slots per token, merge ----
#pragma unroll
        for (int mt = 0; mt < 2; ++mt)
#pragma unroll
            for (int h = 0; h < 2; ++h) {
                int t = wm * 32 + mt * 16 + h * 8 + g8;
                int sl = t * 8 + wn * 4 + c4;
                int li = mt * 2 + h;
                redM1[sl] = fm1[li]; redM2[sl] = fm2[li]; redI[sl] = fi1[li];
            }
        if (tid == 0) cnt = 0;
        __syncthreads();

        if (tid < TM) {
            float m1 = redM1[tid * 8], m2 = redM2[tid * 8];
            int   i1 = redI[tid * 8];
#pragma unroll
            for (int s = 1; s < 8; ++s) {
                float a1 = redM1[tid * 8 + s], a2 = redM2[tid * 8 + s];
                int   ai = redI[tid * 8 + s];
                if (a1 < m1 || (a1 == m1 && ai < i1)) {
                    m2 = fminf(m1, a2); m1 = a1; i1 = ai;
                } else {
                    m2 = fminf(m2, a1);
                }
            }
            // margin decision
            const float* rr = sA + tid * SA_ROWF;
            float rn2 = 0.f;
#pragma unroll
            for (int d = 0; d < DIM; ++d) rn2 = fmaf(rr[d], rr[d], rn2);
            float margin = MARG_CONST * sqrtf(rn2 * __int_as_float(g_maxcn[q]));
            finIdx[tid] = i1;
            if (!(m2 - m1 >= margin)) {          // NaN-safe
                int p = atomicAdd(&cnt, 1);
                list[p] = tid;
            }
        }
        __syncthreads();
        const int rc = cnt;

        // ---- exact rescue (R2-verified pipeline: seq fma, fmaf(-2,dot,cn)) ----
        for (int ri = 0; ri < rc; ++ri) {
            const int t = list[ri];
            const float* rrow = sA + t * SA_ROWF;
            float bv = 3.4e38f; int bi = 0;
#pragma unroll
            for (int rep = 0; rep < 4; ++rep) {
                int k = tid + rep * NTHREADS;
                const float* br = cbq + (size_t)k * DIM;
                float dot = 0.f;
#pragma unroll
                for (int d = 0; d < DIM; ++d) dot = fmaf(rrow[d], __ldg(&br[d]), dot);
                float v = fmaf(-2.0f, dot, sCn[k]);
                if (v < bv || (v == bv && k < bi)) { bv = v; bi = k; }
            }
            rscV[tid] = bv; rscI[tid] = bi;
            __syncthreads();
            if (tid == 0) {
                float b0 = rscV[0]; int b0i = rscI[0];
                for (int i = 1; i < NTHREADS; ++i) {
                    float v = rscV[i]; int ii = rscI[i];
                    if (v < b0 || (v == b0 && ii < b0i)) { b0 = v; b0i = ii; }
                }
                finIdx[t] = b0i;
            }
            __syncthreads();
        }

        if (tid < TM)
            out_idx[(size_t)(n0 + tid) * QSTG + q] = (float)finIdx[tid];
        __syncthreads();

        // ---- residual update + commitment loss (verified code) ----
        {
            const int t = tid >> 1, hd = tid & 1;
            const int idx = finIdx[t];
            const float4* c4p = (const float4*)(cbq + (size_t)idx * DIM + hd * 32);
            float2* r2 = (float2*)(sA + t * SA_ROWF + hd * 32);
            float ls = 0.f;
#pragma unroll
            for (int m = 0; m < 8; ++m) {
                float4 cv = c4p[m];
                float2 ra = r2[2 * m], rb = r2[2 * m + 1];
                float2 na, nb;
                na.x = __fsub_rn(ra.x, cv.x);
                na.y = __fsub_rn(ra.y, cv.y);
                nb.x = __fsub_rn(rb.x, cv.z);
                nb.y = __fsub_rn(rb.y, cv.w);
                r2[2 * m]     = na;
                r2[2 * m + 1] = nb;
                ls = fmaf(na.x, na.x, ls);
                ls = fmaf(na.y, na.y, ls);
                ls = fmaf(nb.x, nb.x, ls);
                ls = fmaf(nb.y, nb.y, ls);
            }
#pragma unroll
            for (int off = 16; off; off >>= 1)
                ls += __shfl_down_sync(0xffffffff, ls, off);
            if ((tid & 31) == 0) wsum[tid >> 5] = ls;
            __syncthreads();
            if (tid == 0) {
                float tot = 0.f;
#pragma unroll
                for (int w = 0; w < NTHREADS / 32; ++w) tot += wsum[w];
                atomicAdd(&g_loss[q], (double)tot);
            }
        }
        __syncthreads();   // sA update visible before next stage conversion
    }

    // ---- xq = x - final residual ----
    {
        const int t = tid >> 1, hd = tid & 1;
        const float2* xr = (const float2*)(x + (size_t)(n0 + t) * DIM + hd * 32);
        const float2* rr = (const float2*)(sA + t * SA_ROWF + hd * 32);
        float2* o2 = (float2*)(out_xq + (size_t)(n0 + t) * DIM + hd * 32);
#pragma unroll
        for (int m = 0; m < 16; ++m) {
            float2 xv = xr[m], rv = rr[m], ov;
            ov.x = __fsub_rn(xv.x, rv.x);
            ov.y = __fsub_rn(xv.y, rv.y);
            o2[m] = ov;
        }
    }
}

// ---------------------------------------------------------------------------
__global__ void loss_kernel(float* __restrict__ out) {
    if (threadIdx.x < QSTG)
        out[(size_t)N_TOK * DIM + (size_t)N_TOK * QSTG + threadIdx.x] =
            (float)(g_loss[threadIdx.x] / (double)((size_t)N_TOK * DIM));
}

extern "C" void kernel_launch(void* const* d_in, const int* in_sizes, int n_in,
                              void* d_out, int out_size) {
    const float* x  = (const float*)d_in[0];
    const float* cb = (const float*)d_in[1];
    if (n_in >= 2 && in_sizes[0] == QSTG * KCB * DIM && in_sizes[1] == N_TOK * DIM) {
        const float* t = x; x = cb; cb = t;
    }
    float* out = (float*)d_out;

    cudaFuncSetAttribute(vq_kernel,
                         cudaFuncAttributeMaxDynamicSharedMemorySize, SMEM_BYTES);

    prep_kernel<<<(QSTG * KCB + 255) / 256, 256>>>(cb);
    prep_bimg_kernel<<<NGBLK, NTHREADS>>>(cb);
    vq_kernel<<<N_TOK / TM, NTHREADS, SMEM_BYTES>>>(x, cb, out);
    loss_kernel<<<1, 32>>>(out);
}

// round 13
// speedup vs baseline: 1.5181x; 1.5181x over previous
#include <cuda_runtime.h>
#include <cstdint>

#define N_TOK 131072
#define DIM   64
#define QSTG  8
#define KCB   1024

#define TM       128            // tokens per CTA
#define TKC      256            // codewords per SMEM chunk
#define NCHUNK   (KCB / TKC)    // 4
#define NTHREADS 256

typedef unsigned long long ull;

// dynamic smem layout (floats):
//   sA   [TM][DIM]                 : 8192
//   sBt  64 rows x 1024 B (pairs)  : 16384   (row d holds 128 pairs (B[2k][d],B[2k+1][d]), slot = k ^ (d>>2))
//   sCn  [TKC]                     : 256
#define SA_F    0
#define SBT_F   (TM * DIM)                  // 8192
#define SCN_F   (SBT_F + 64 * 256)          // 8192 + 16384
#define SMEM_FLOATS (SCN_F + TKC)
#define SMEM_BYTES  (SMEM_FLOATS * 4)

__device__ double g_loss[QSTG];
__device__ float  g_cnorm[QSTG * KCB];

__device__ __forceinline__ void ffma2(ull& d, ull a, ull b) {
    asm("fma.rn.f32x2 %0, %1, %2, %0;" : "+l"(d) : "l"(a), "l"(b));
}
__device__ __forceinline__ ull dup2(float a) {
    ull r; unsigned u = __float_as_uint(a);
    asm("mov.b64 %0, {%1, %1};" : "=l"(r) : "r"(u));
    return r;
}
__device__ __forceinline__ float2 unpack2(ull v) {
    float2 r;
    asm("mov.b64 {%0, %1}, %2;" : "=f"(r.x), "=f"(r.y) : "l"(v));
    return r;
}

// ---------------------------------------------------------------------------
// prep: codeword squared norms + zero loss accumulators
// ---------------------------------------------------------------------------
__global__ void prep_kernel(const float* __restrict__ cb) {
    int k = blockIdx.x * blockDim.x + threadIdx.x;
    if (k < QSTG * KCB) {
        const float* p = cb + (size_t)k * DIM;
        float s0 = 0.f, s1 = 0.f, s2 = 0.f, s3 = 0.f;
#pragma unroll
        for (int d = 0; d < DIM; d += 4) {
            s0 = __fadd_rn(s0, __fmul_rn(p[d + 0], p[d + 0]));
            s1 = __fadd_rn(s1, __fmul_rn(p[d + 1], p[d + 1]));
            s2 = __fadd_rn(s2, __fmul_rn(p[d + 2], p[d + 2]));
            s3 = __fadd_rn(s3, __fmul_rn(p[d + 3], p[d + 3]));
        }
        g_cnorm[k] = __fadd_rn(__fadd_rn(s0, s1), __fadd_rn(s2, s3));
    }
    if (blockIdx.x == 0 && threadIdx.x < QSTG) g_loss[threadIdx.x] = 0.0;
}

// ---------------------------------------------------------------------------
// fused: all 8 VQ stages for one 128-token tile (residual stays in SMEM)
// ---------------------------------------------------------------------------
__global__ void __launch_bounds__(NTHREADS, 1)
vq_kernel(const float* __restrict__ x, const float* __restrict__ cb,
          float* __restrict__ out) {
    extern __shared__ float sm[];
    float* sA  = sm + SA_F;
    float* sBt = sm + SBT_F;
    float* sCn = sm + SCN_F;
    // reduction overlay (reuses sBt region between chunk phases)
    float* redV = sBt;                        // [TM][16]
    int*   redI = (int*)(sBt + TM * 16);      // [TM][16]
    __shared__ int   finIdx[TM];
    __shared__ float wsum[NTHREADS / 32];

    const int tid  = threadIdx.x;
    const int tokg = tid >> 4;    // 0..15 : 8 tokens each
    const int cwg  = tid & 15;    // 0..15 : 8 codeword-pairs per chunk
    const int n0   = blockIdx.x * TM;

    float* out_xq  = out;
    float* out_idx = out + (size_t)N_TOK * DIM;

    // ---- load token tile once ----
    {
        const float4* gin = (const float4*)(x + (size_t)n0 * DIM);
        float4* sA4 = (float4*)sA;
#pragma unroll
        for (int i = tid; i < TM * DIM / 4; i += NTHREADS) sA4[i] = gin[i];
    }

    for (int q = 0; q < QSTG; ++q) {
        const float* cbq = cb + (size_t)q * KCB * DIM;

        float bestv[8];
        int   besti[8];
#pragma unroll
        for (int ti = 0; ti < 8; ++ti) { bestv[ti] = 3.4e38f; besti[ti] = 0; }

        for (int ch = 0; ch < NCHUNK; ++ch) {
            const int k0 = ch * TKC;
            __syncthreads();   // previous users of sBt / sA writers done

            // ---- stage B chunk as transposed pairs, swizzled slot = p ^ (d>>2) ----
            {
                const float4* gb = (const float4*)(cbq + (size_t)k0 * DIM);
#pragma unroll
                for (int it = 0; it < 8; ++it) {
                    int L = it * NTHREADS + tid;       // 0..2047
                    int p  = L >> 4;                   // pair index 0..127
                    int dq = L & 15;                   // d quad 0..15
                    float4 v1 = gb[(2 * p) * 16 + dq];
                    float4 v2 = gb[(2 * p + 1) * 16 + dq];
                    const float* a1 = &v1.x;
                    const float* a2 = &v2.x;
                    int swz = p ^ dq;
#pragma unroll
                    for (int m = 0; m < 4; ++m) {
                        float2* dst = (float2*)((char*)sBt + (size_t)(4 * dq + m) * 1024) + swz;
                        *dst = make_float2(a1[m], a2[m]);
                    }
                }
                sCn[tid] = g_cnorm[q * KCB + k0 + tid];
            }
            __syncthreads();

            // ---- 8 tokens x 8 codeword-pairs register tile ----
            ull acc[64];
#pragma unroll
            for (int c = 0; c < 64; ++c) acc[c] = 0ull;

            const float* aTok = sA + tokg * 8 * DIM;
#pragma unroll 4
            for (int d = 0; d < DIM; ++d) {
                ull a2r[8];
#pragma unroll
                for (int ti = 0; ti < 8; ++ti)
                    a2r[ti] = dup2(aTok[ti * DIM + d]);
                const ull* bRow = (const ull*)((char*)sBt + (size_t)d * 1024) + (cwg ^ (d >> 2));
                ull b2r[8];
#pragma unroll
                for (int j = 0; j < 8; ++j) b2r[j] = bRow[16 * j];
#pragma unroll
                for (int ti = 0; ti < 8; ++ti)
#pragma unroll
                    for (int j = 0; j < 8; ++j)
                        ffma2(acc[ti * 8 + j], a2r[ti], b2r[j]);
            }

            // ---- running argmin: val = cnorm - 2*dot  (rnorm is a per-token constant) ----
#pragma unroll
            for (int j = 0; j < 8; ++j) {
                const int kl = 2 * (cwg + 16 * j);
                const float2 cn = *(const float2*)(sCn + kl);
                const int kg = k0 + kl;
#pragma unroll
                for (int ti = 0; ti < 8; ++ti) {
                    float2 p = unpack2(acc[ti * 8 + j]);
                    float v0 = fmaf(-2.0f, p.x, cn.x);
                    float v1 = fmaf(-2.0f, p.y, cn.y);
                    bool l0 = v0 < bestv[ti];
                    bestv[ti] = l0 ? v0 : bestv[ti];
                    besti[ti] = l0 ? kg : besti[ti];
                    bool l1 = v1 < bestv[ti];
                    bestv[ti] = l1 ? v1 : bestv[ti];
                    besti[ti] = l1 ? (kg + 1) : besti[ti];
                }
            }
        }
        __syncthreads();

        // ---- cross-thread argmin (16 partials per token), index tiebreak ----
#pragma unroll
        for (int ti = 0; ti < 8; ++ti) {
            int t = tokg * 8 + ti;
            redV[t * 16 + cwg] = bestv[ti];
            redI[t * 16 + cwg] = besti[ti];
        }
        __syncthreads();
        if (tid < TM) {
            float bv = redV[tid * 16];
            int   bi = redI[tid * 16];
#pragma unroll
            for (int g = 1; g < 16; ++g) {
                float v  = redV[tid * 16 + g];
                int   ii = redI[tid * 16 + g];
                if (v < bv || (v == bv && ii < bi)) { bv = v; bi = ii; }
            }
            finIdx[tid] = bi;
            out_idx[(size_t)(n0 + tid) * QSTG + q] = (float)bi;
        }
        __syncthreads();

        // ---- residual update (in SMEM) + commitment loss ----
        {
            const int t = tid >> 1, h = tid & 1;
            const int idx = finIdx[t];
            const float4* c4 = (const float4*)(cbq + (size_t)idx * DIM + h * 32);
            float4* r4 = (float4*)(sA + t * DIM + h * 32);
            float ls = 0.f;
#pragma unroll
            for (int m = 0; m < 8; ++m) {
                float4 rv = r4[m], cv = c4[m], nv;
                nv.x = __fsub_rn(rv.x, cv.x);
                nv.y = __fsub_rn(rv.y, cv.y);
                nv.z = __fsub_rn(rv.z, cv.z);
                nv.w = __fsub_rn(rv.w, cv.w);
                r4[m] = nv;
                ls = fmaf(nv.x, nv.x, ls);
                ls = fmaf(nv.y, nv.y, ls);
                ls = fmaf(nv.z, nv.z, ls);
                ls = fmaf(nv.w, nv.w, ls);
            }
#pragma unroll
            for (int off = 16; off; off >>= 1)
                ls += __shfl_down_sync(0xffffffff, ls, off);
            if ((tid & 31) == 0) wsum[tid >> 5] = ls;
            __syncthreads();
            if (tid == 0) {
                float tot = 0.f;
#pragma unroll
                for (int w = 0; w < NTHREADS / 32; ++w) tot += wsum[w];
                atomicAdd(&g_loss[q], (double)tot);
            }
        }
    }
    __syncthreads();

    // ---- xq = x - final_residual ----
    {
        const float4* x4 = (const float4*)(x + (size_t)n0 * DIM);
        const float4* r4 = (const float4*)sA;
        float4* o4 = (float4*)(out_xq + (size_t)n0 * DIM);
#pragma unroll
        for (int i = tid; i < TM * DIM / 4; i += NTHREADS) {
            float4 xv = x4[i], rv = r4[i], ov;
            ov.x = __fsub_rn(xv.x, rv.x);
            ov.y = __fsub_rn(xv.y, rv.y);
            ov.z = __fsub_rn(xv.z, rv.z);
            ov.w = __fsub_rn(xv.w, rv.w);
            o4[i] = ov;
        }
    }
}

// ---------------------------------------------------------------------------
// losses
// ---------------------------------------------------------------------------
__global__ void loss_kernel(float* __restrict__ out) {
    if (threadIdx.x < QSTG)
        out[(size_t)N_TOK * DIM + (size_t)N_TOK * QSTG + threadIdx.x] =
            (float)(g_loss[threadIdx.x] / (double)((size_t)N_TOK * DIM));
}

extern "C" void kernel_launch(void* const* d_in, const int* in_sizes, int n_in,
                              void* d_out, int out_size) {
    const float* x  = (const float*)d_in[0];
    const float* cb = (const float*)d_in[1];
    if (n_in >= 2 && in_sizes[0] == QSTG * KCB * DIM && in_sizes[1] == N_TOK * DIM) {
        const float* t = x; x = cb; cb = t;
    }
    float* out = (float*)d_out;

    cudaFuncSetAttribute(vq_kernel,
                         cudaFuncAttributeMaxDynamicSharedMemorySize, SMEM_BYTES);

    prep_kernel<<<(QSTG * KCB + 255) / 256, 256>>>(cb);
    vq_kernel<<<N_TOK / TM, NTHREADS, SMEM_BYTES>>>(x, cb, out);
    loss_kernel<<<1, 32>>>(out);
}